// round 15
// baseline (speedup 1.0000x reference)
#include <cuda_runtime.h>
#include <cuda_fp16.h>

// Problem dims
#define BB 8
#define HH 640
#define WW 368
#define HW (HH*WW)            // 235520
#define NTOT (BB*HH*WW)       // 1884160

// Static device scratch
__device__ float2 g_bufA[NTOT];   // conv output as complex, [b][h][w]
__device__ float2 g_bufB[NTOT];   // after W-FFT, transposed: [b][w][h]
__device__ __half g_midT[NTOT];   // |ifft| (fp16-quantized), [b][w][h]

// ---------------- packed f32x2 helpers ----------------
__device__ __forceinline__ unsigned long long pk2(float lo, float hi){
    unsigned long long r; asm("mov.b64 %0, {%1,%2};" : "=l"(r) : "f"(lo), "f"(hi)); return r;
}
__device__ __forceinline__ void upk2(unsigned long long v, float& lo, float& hi){
    asm("mov.b64 {%0,%1}, %2;" : "=f"(lo), "=f"(hi) : "l"(v));
}
__device__ __forceinline__ unsigned long long ffma2(unsigned long long a, unsigned long long b, unsigned long long c){
    unsigned long long d; asm("fma.rn.f32x2 %0, %1, %2, %3;" : "=l"(d) : "l"(a), "l"(b), "l"(c)); return d;
}
__device__ __forceinline__ unsigned long long fmul2(unsigned long long a, unsigned long long b){
    unsigned long long d; asm("mul.rn.f32x2 %0, %1, %2;" : "=l"(d) : "l"(a), "l"(b)); return d;
}
__device__ __forceinline__ unsigned long long fadd2(unsigned long long a, unsigned long long b){
    unsigned long long d; asm("add.rn.f32x2 %0, %1, %2;" : "=l"(d) : "l"(a), "l"(b)); return d;
}
// packed leaky: 0.505*x + 0.495*|x|
__device__ __forceinline__ unsigned long long leaky2(unsigned long long x,
                                                     unsigned long long cA,
                                                     unsigned long long cB){
    unsigned long long ax;
    asm("and.b64 %0, %1, 0x7FFFFFFF7FFFFFFF;" : "=l"(ax) : "l"(x));
    return ffma2(x, cA, fmul2(ax, cB));
}
__device__ __forceinline__ float sqrt_approx(float x){
    float r; asm("sqrt.approx.f32 %0, %1;" : "=f"(r) : "f"(x)); return r;
}

// ---------------- complex helpers (IFFT sign: e^{+2 pi i / N}) ----------------
__device__ __forceinline__ float2 cadd(float2 a, float2 b){ return make_float2(a.x+b.x, a.y+b.y); }
__device__ __forceinline__ float2 csub(float2 a, float2 b){ return make_float2(a.x-b.x, a.y-b.y); }
__device__ __forceinline__ float2 cmul(float2 a, float2 b){
    return make_float2(fmaf(a.x,b.x,-(a.y*b.y)), fmaf(a.x,b.y, a.y*b.x));
}
__device__ __forceinline__ float2 cmuli(float2 a){ return make_float2(-a.y, a.x); }

__device__ __forceinline__ void dft4p(float2 a, float2 b, float2 c, float2 d,
                                      float2& x0, float2& x1, float2& x2, float2& x3){
    float2 t0 = cadd(a,c), t1 = csub(a,c), t2 = cadd(b,d), t3 = csub(b,d);
    x0 = cadd(t0,t2); x2 = csub(t0,t2);
    float2 it3 = cmuli(t3);
    x1 = cadd(t1,it3); x3 = csub(t1,it3);
}

#define R2F  0.70710678118654752f
#define C8F  0.92387953251128674f
#define S8F  0.38268343236508977f

__device__ __forceinline__ void fft16(float2 v[16]){
    float2 Bm[4][4];
    #pragma unroll
    for (int n1=0;n1<4;n1++)
        dft4p(v[n1], v[n1+4], v[n1+8], v[n1+12], Bm[n1][0],Bm[n1][1],Bm[n1][2],Bm[n1][3]);
    Bm[1][1] = cmul(Bm[1][1], make_float2( C8F,  S8F));
    Bm[1][2] = cmul(Bm[1][2], make_float2( R2F,  R2F));
    Bm[1][3] = cmul(Bm[1][3], make_float2( S8F,  C8F));
    Bm[2][1] = cmul(Bm[2][1], make_float2( R2F,  R2F));
    Bm[2][2] = cmuli(Bm[2][2]);
    Bm[2][3] = cmul(Bm[2][3], make_float2(-R2F,  R2F));
    Bm[3][1] = cmul(Bm[3][1], make_float2( S8F,  C8F));
    Bm[3][2] = cmul(Bm[3][2], make_float2(-R2F,  R2F));
    Bm[3][3] = cmul(Bm[3][3], make_float2(-C8F, -S8F));
    #pragma unroll
    for (int k2=0;k2<4;k2++)
        dft4p(Bm[0][k2],Bm[1][k2],Bm[2][k2],Bm[3][k2], v[k2], v[k2+4], v[k2+8], v[k2+12]);
}

__device__ __forceinline__ void fft8(float2 v[8]){
    float2 E0,E1,E2,E3,O0,O1,O2,O3;
    dft4p(v[0],v[2],v[4],v[6], E0,E1,E2,E3);
    dft4p(v[1],v[3],v[5],v[7], O0,O1,O2,O3);
    O1 = cmul(O1, make_float2( R2F, R2F));
    O2 = cmuli(O2);
    O3 = cmul(O3, make_float2(-R2F, R2F));
    v[0]=cadd(E0,O0); v[4]=csub(E0,O0);
    v[1]=cadd(E1,O1); v[5]=csub(E1,O1);
    v[2]=cadd(E2,O2); v[6]=csub(E2,O2);
    v[3]=cadd(E3,O3); v[7]=csub(E3,O3);
}

__device__ __forceinline__ void dft5p(float2 x0,float2 x1,float2 x2,float2 x3,float2 x4, float2* X){
    const float c1 =  0.30901699437494742f, s1 = 0.95105651629515357f;
    const float c2 = -0.80901699437494742f, s2 = 0.58778525229247312f;
    float2 t1=cadd(x1,x4), t2=csub(x1,x4), t3=cadd(x2,x3), t4=csub(x2,x3);
    X[0] = cadd(x0, cadd(t1,t3));
    float2 a1 = make_float2(x0.x + c1*t1.x + c2*t3.x, x0.y + c1*t1.y + c2*t3.y);
    float2 b1 = make_float2(s1*t2.x + s2*t4.x,        s1*t2.y + s2*t4.y);
    float2 a2 = make_float2(x0.x + c2*t1.x + c1*t3.x, x0.y + c2*t1.y + c1*t3.y);
    float2 b2 = make_float2(s2*t2.x - s1*t4.x,        s2*t2.y - s1*t4.y);
    float2 ib1 = cmuli(b1), ib2 = cmuli(b2);
    X[1]=cadd(a1,ib1); X[4]=csub(a1,ib1);
    X[2]=cadd(a2,ib2); X[3]=csub(a2,ib2);
}

// diagnostic filler: shifts the ncu capture index (abs launch 3) onto k_conv1
__global__ void k_nop(){}

// ===== Pass 1: Winograd F(4,3) conv3x3(2->32)+leaky + conv1x1(32->2)+leaky. =====
__global__ __launch_bounds__(128) void k_conv1(const float* __restrict__ ks,
                                               const float* __restrict__ wk,
                                               const float* __restrict__ bk,
                                               const float* __restrict__ w1,
                                               const float* __restrict__ b1){
    __shared__ unsigned long long s_U[32*36];
    __shared__ ulonglong2 s_bw[32];
    __shared__ unsigned long long s_w1b[32];
    __shared__ float s_b1[2];
    int tid = threadIdx.x;

    for (int t=tid; t<192; t+=128){
        int o = t/6, rw = t%6;
        float g0 = wk[o*18 + rw*3 + 0];
        float g1 = wk[o*18 + rw*3 + 1];
        float g2 = wk[o*18 + rw*3 + 2];
        float u0 = 0.25f*g0;
        float u1 = -(g0+g1+g2)*(1.f/6.f);
        float u2 = (g1-g0-g2)*(1.f/6.f);
        float u3 = fmaf(2.f,g1, fmaf(4.f,g2, g0))*(1.f/24.f);
        float u4 = fmaf(-2.f,g1, fmaf(4.f,g2, g0))*(1.f/24.f);
        float u5 = g2;
        unsigned long long* Uo = &s_U[o*36 + rw*6];
        Uo[0]=pk2(u0,u0); Uo[1]=pk2(u1,u1); Uo[2]=pk2(u2,u2);
        Uo[3]=pk2(u3,u3); Uo[4]=pk2(u4,u4); Uo[5]=pk2(u5,u5);
    }
    if (tid<32){
        float v=bk[tid]; float a=w1[tid]; float bq=w1[32+tid];
        s_bw[tid] = make_ulonglong2(pk2(v,v), pk2(a,a));
        s_w1b[tid]= pk2(bq,bq);
    }
    if (tid<2)  s_b1[tid]=b1[tid];
    __syncthreads();

    int t = blockIdx.x*blockDim.x + tid;            // thread = 8 px
    int g   = t % 46;
    int row = t / 46;
    int h = row % HH;
    int b = row / HH;
    int w0 = g*8;

    const unsigned long long c2p  = pk2( 2.f, 2.f);
    const unsigned long long cm2p = pk2(-2.f,-2.f);
    const unsigned long long c4p  = pk2( 4.f, 4.f);
    const unsigned long long cm4p = pk2(-4.f,-4.f);
    const unsigned long long cm5p = pk2(-5.f,-5.f);
    const unsigned long long c8p  = pk2( 8.f, 8.f);
    const unsigned long long cm1p = pk2(-1.f,-1.f);

    unsigned long long tp[36];
    #pragma unroll
    for (int c=0;c<2;c++){
        const float* base = ks + (size_t)(b*2+c)*HW;
        #pragma unroll
        for (int kh=0;kh<3;kh++){
            int hh = h + kh - 1;
            float4 f1 = make_float4(0.f,0.f,0.f,0.f);
            float4 f2 = f1;
            float xm1 = 0.f, xp8 = 0.f;
            if (hh>=0 && hh<HH){
                const float* rp = base + (size_t)hh*WW + w0;
                f1 = *(const float4*)rp;
                f2 = *(const float4*)(rp+4);
                xm1 = (g>0)  ? __ldg(rp-1) : 0.f;
                xp8 = (g<45) ? __ldg(rp+8) : 0.f;
            }
            unsigned long long dp0 = pk2(xm1,  f1.w);
            unsigned long long dp1 = pk2(f1.x, f2.x);
            unsigned long long dp2 = pk2(f1.y, f2.y);
            unsigned long long dp3 = pk2(f1.z, f2.z);
            unsigned long long dp4 = pk2(f1.w, f2.w);
            unsigned long long dp5 = pk2(f2.x, xp8);
            unsigned long long* tr = &tp[(c*3+kh)*6];
            tr[0] = ffma2(dp0, c4p, ffma2(dp2, cm5p, dp4));
            tr[1] = ffma2(fadd2(dp1,dp2), cm4p, fadd2(dp3,dp4));
            unsigned long long d12 = ffma2(dp2, cm1p, dp1);
            unsigned long long d43 = ffma2(dp3, cm1p, dp4);
            tr[2] = ffma2(d12, c4p, d43);
            unsigned long long e = ffma2(dp1, cm1p, dp3);
            unsigned long long f = ffma2(dp2, cm1p, dp4);
            tr[3] = ffma2(e, c2p,  f);
            tr[4] = ffma2(e, cm2p, f);
            tr[5] = ffma2(dp1, c4p, ffma2(dp3, cm5p, dp5));
        }
    }

    unsigned long long acc0[4], acc1[4];
    {
        unsigned long long b0 = pk2(s_b1[0], s_b1[0]);
        unsigned long long b1p = pk2(s_b1[1], s_b1[1]);
        #pragma unroll
        for (int j=0;j<4;j++){ acc0[j]=b0; acc1[j]=b1p; }
    }
    const unsigned long long cA = pk2(0.505f,0.505f);
    const unsigned long long cB = pk2(0.495f,0.495f);

    #pragma unroll 2
    for (int o=0;o<32;o++){
        const ulonglong2* Uo2 = (const ulonglong2*)&s_U[o*36];
        unsigned long long m0,m1,m2,m3,m4,m5;
        {
            ulonglong2 u01 = Uo2[0], u23 = Uo2[1], u45 = Uo2[2];
            m0 = fmul2(u01.x, tp[0]); m1 = fmul2(u01.y, tp[1]);
            m2 = fmul2(u23.x, tp[2]); m3 = fmul2(u23.y, tp[3]);
            m4 = fmul2(u45.x, tp[4]); m5 = fmul2(u45.y, tp[5]);
        }
        #pragma unroll
        for (int rw=1;rw<6;rw++){
            ulonglong2 u01 = Uo2[rw*3+0], u23 = Uo2[rw*3+1], u45 = Uo2[rw*3+2];
            const unsigned long long* tr = &tp[rw*6];
            m0 = ffma2(u01.x, tr[0], m0);
            m1 = ffma2(u01.y, tr[1], m1);
            m2 = ffma2(u23.x, tr[2], m2);
            m3 = ffma2(u23.y, tr[3], m3);
            m4 = ffma2(u45.x, tr[4], m4);
            m5 = ffma2(u45.y, tr[5], m5);
        }
        ulonglong2 bw = s_bw[o];
        unsigned long long bkp = bw.x, wa = bw.y;
        unsigned long long wb = s_w1b[o];
        unsigned long long ta = fadd2(m1,m2);
        unsigned long long tb = ffma2(m2, cm1p, m1);
        unsigned long long tc = fadd2(m3,m4);
        unsigned long long td = ffma2(m4, cm1p, m3);
        unsigned long long y0 = fadd2(fadd2(m0,ta), fadd2(tc,bkp));
        unsigned long long y1 = ffma2(td, c2p, fadd2(tb,bkp));
        unsigned long long y2 = ffma2(tc, c4p, fadd2(ta,bkp));
        unsigned long long y3 = ffma2(td, c8p, fadd2(tb, fadd2(m5,bkp)));
        y0 = leaky2(y0, cA, cB); y1 = leaky2(y1, cA, cB);
        y2 = leaky2(y2, cA, cB); y3 = leaky2(y3, cA, cB);
        acc0[0] = ffma2(wa, y0, acc0[0]);  acc1[0] = ffma2(wb, y0, acc1[0]);
        acc0[1] = ffma2(wa, y1, acc0[1]);  acc1[1] = ffma2(wb, y1, acc1[1]);
        acc0[2] = ffma2(wa, y2, acc0[2]);  acc1[2] = ffma2(wb, y2, acc1[2]);
        acc0[3] = ffma2(wa, y3, acc0[3]);  acc1[3] = ffma2(wb, y3, acc1[3]);
    }

    float r[8], im[8];
    #pragma unroll
    for (int j=0;j<4;j++){
        float lo,hi;
        upk2(acc0[j],lo,hi); r[j]  = fmaxf(lo,0.01f*lo); r[4+j]  = fmaxf(hi,0.01f*hi);
        upk2(acc1[j],lo,hi); im[j] = fmaxf(lo,0.01f*lo); im[4+j] = fmaxf(hi,0.01f*hi);
    }
    float sg = ((b+h)&1) ? -1.f : 1.f;     // w0 even
    float4* dst = (float4*)&g_bufA[(size_t)row*WW + w0];
    #pragma unroll
    for (int k2=0;k2<4;k2++){
        dst[k2] = make_float4( sg*r[2*k2],  sg*im[2*k2], -sg*r[2*k2+1], -sg*im[2*k2+1]);
    }
}

// ===== Pass 2: W-FFT (368 = 23 x 16), 8 rows/block, 128 threads =====
#define FFTW_ROWS 8
#define ROWSTRIDE 369
#define FFTW_SMEM (FFTW_ROWS*ROWSTRIDE*8 + 368*8 + 23*8*2)

__global__ __launch_bounds__(128) void k_fftw(){
    extern __shared__ unsigned char dsm[];
    float2* S     = (float2*)dsm;
    float2* tw368 = (float2*)(dsm + FFTW_ROWS*ROWSTRIDE*8);
    unsigned long long* twc = (unsigned long long*)(dsm + FFTW_ROWS*ROWSTRIDE*8 + 368*8);
    unsigned long long* tws = twc + 23;

    int b  = blockIdx.x / 80;
    int h0 = (blockIdx.x % 80) * FFTW_ROWS;
    int tid = threadIdx.x;
    const float2* src = g_bufA + (size_t)(b*HH + h0)*WW;

    for (int m=tid;m<368;m+=128){ float sn,cs; sincospif((float)m*(1.f/184.f), &sn,&cs); tw368[m]=make_float2(cs,sn); }
    if (tid < 23){ float sn,cs; sincospif((float)tid*(2.f/23.f), &sn,&cs); twc[tid]=pk2(cs,cs); tws[tid]=pk2(sn,sn); }

    cudaGridDependencySynchronize();

    for (int t=tid; t<FFTW_ROWS*184; t+=128){
        int r = t / 184, c2 = t % 184;
        float4 v = ((const float4*)src)[t];
        float2* drow = &S[r*ROWSTRIDE + 2*c2];
        drow[0] = make_float2(v.x, v.y);
        drow[1] = make_float2(v.z, v.w);
    }
    __syncthreads();

    for (int t=tid; t<FFTW_ROWS*23; t+=128){
        int r = t / 23, n1 = t % 23;
        float2* rowp = &S[r*ROWSTRIDE];
        float2 v[16];
        #pragma unroll
        for (int j=0;j<16;j++) v[j] = rowp[n1 + 23*j];
        fft16(v);
        #pragma unroll
        for (int k2=1;k2<16;k2++) v[k2] = cmul(v[k2], tw368[n1*k2]);
        #pragma unroll
        for (int k2=0;k2<16;k2++) rowp[n1 + 23*k2] = v[k2];
    }
    __syncthreads();

    {
        int r = tid >> 4, k2 = tid & 15;
        float2* rowp = &S[r*ROWSTRIDE];
        float2 a[23];
        #pragma unroll
        for (int n=0;n<23;n++) a[n] = rowp[23*k2 + n];
        __syncthreads();

        float2 a0 = a[0];
        unsigned long long ps[11], pd[11];
        float2 x0 = a0;
        #pragma unroll
        for (int n=1;n<=11;n++){
            float2 s = cadd(a[n], a[23-n]);
            float2 d = csub(a[n], a[23-n]);
            x0 = cadd(x0, s);
            ps[n-1] = pk2(s.x, s.y);
            pd[n-1] = pk2(d.x, d.y);
        }
        rowp[k2] = x0;
        unsigned long long pa0 = pk2(a0.x, a0.y);
        const unsigned long long pz = pk2(0.f, 0.f);
        for (int k=1;k<=11;k++){
            unsigned long long C = pa0, Sm = pz;
            int m = 0;
            #pragma unroll
            for (int n=1;n<=11;n++){
                m += k; if (m >= 23) m -= 23;
                C  = ffma2(ps[n-1], twc[m], C);
                Sm = ffma2(pd[n-1], tws[m], Sm);
            }
            float Cx,Cy,Sx,Sy;
            upk2(C,Cx,Cy); upk2(Sm,Sx,Sy);
            rowp[k2 + 16*k]      = make_float2(Cx - Sy, Cy + Sx);
            rowp[k2 + 16*(23-k)] = make_float2(Cx + Sy, Cy - Sx);
        }
    }
    __syncthreads();

    for (int i=tid;i<FFTW_ROWS*368;i+=128){
        int r2 = i & 7; int w = i >> 3;
        g_bufB[(size_t)(b*WW + w)*HH + h0 + r2] = S[r2*ROWSTRIDE + w];
    }
}

// ===== Pass 3: H-FFT + B-DFT-8 + abs; PDL: twiddles before grid sync =====
#define HROW 740
#define HCHUNK 148
#define FFTHB_SMEM (8*HROW*8 + 640*8 + 128*8)

__global__ __launch_bounds__(640) void k_ffthb(){
    extern __shared__ unsigned char dsm[];
    float2* S    = (float2*)dsm;
    float2* W640 = (float2*)(dsm + 8*HROW*8);
    float2* W128 = (float2*)(dsm + 8*HROW*8 + 640*8);
    int w   = blockIdx.x;
    int tid = threadIdx.x;

    { float sn,cs; sincospif((float)tid*(1.f/320.f),&sn,&cs); W640[tid]=make_float2(cs,sn); }
    if (tid<128){ float sn,cs; sincospif((float)tid*(1.f/64.f),&sn,&cs); W128[tid]=make_float2(cs,sn); }

    cudaGridDependencySynchronize();

    for (int i=tid;i<8*640;i+=640){
        int bb = i/640, h = i%640;
        S[bb*HROW + h] = g_bufB[(size_t)(bb*WW + w)*HH + h];
    }
    __syncthreads();

    {
        float2 Xa[5], Xb[5];
        int rowa = tid >> 7, n2a = tid & 127;
        {
            float2* col = &S[rowa*HROW];
            dft5p(col[n2a], col[n2a+128], col[n2a+256], col[n2a+384], col[n2a+512], Xa);
            #pragma unroll
            for (int k1=1;k1<5;k1++) Xa[k1] = cmul(Xa[k1], W640[n2a*k1]);
        }
        int rowb = 0, n2b = 0;
        if (tid < 384){
            int t2 = tid + 640;
            rowb = t2 >> 7; n2b = t2 & 127;
            float2* col = &S[rowb*HROW];
            dft5p(col[n2b], col[n2b+128], col[n2b+256], col[n2b+384], col[n2b+512], Xb);
            #pragma unroll
            for (int k1=1;k1<5;k1++) Xb[k1] = cmul(Xb[k1], W640[n2b*k1]);
        }
        __syncthreads();
        {
            int p2 = (n2a>>3) + 17*(n2a&7);
            float2* rowp = &S[rowa*HROW];
            #pragma unroll
            for (int k1=0;k1<5;k1++) rowp[k1*HCHUNK + p2] = Xa[k1];
        }
        if (tid < 384){
            int p2 = (n2b>>3) + 17*(n2b&7);
            float2* rowp = &S[rowb*HROW];
            #pragma unroll
            for (int k1=0;k1<5;k1++) rowp[k1*HCHUNK + p2] = Xb[k1];
        }
    }
    __syncthreads();

    {
        float2 v[16];
        int brow=0, chunk=0, m1=0;
        bool act = (tid < 320);
        if (act){
            brow = tid/40; int rest = tid%40; chunk = rest/8; m1 = rest%8;
            float2* base = &S[brow*HROW + chunk*HCHUNK];
            #pragma unroll
            for (int m2=0;m2<16;m2++) v[m2] = base[m2 + 17*m1];
            fft16(v);
            #pragma unroll
            for (int kk=1;kk<16;kk++) v[kk] = cmul(v[kk], W128[m1*kk]);
        }
        __syncthreads();
        if (act){
            float2* base = &S[brow*HROW + chunk*HCHUNK];
            #pragma unroll
            for (int kk=0;kk<16;kk++) base[m1 + 9*kk] = v[kk];
        }
    }
    __syncthreads();

    {
        int brow = tid/80; int rest = tid%80; int k1 = rest/16; int q2 = rest%16;
        float2* rowp = &S[brow*HROW];
        float2 v[8];
        #pragma unroll
        for (int m1=0;m1<8;m1++) v[m1] = rowp[k1*HCHUNK + m1 + 9*q2];
        __syncthreads();
        fft8(v);
        #pragma unroll
        for (int q1=0;q1<8;q1++) rowp[k1 + 5*(q2 + 16*q1)] = v[q1];
    }
    __syncthreads();

    {
        int h = tid;
        float2 v[8];
        #pragma unroll
        for (int bb=0;bb<8;bb++) v[bb] = S[bb*HROW + h];
        fft8(v);
        const float SC = 7.2851736e-4f;
        #pragma unroll
        for (int kb=0;kb<8;kb++){
            float im = SC * sqrt_approx(fmaf(v[kb].x, v[kb].x, v[kb].y*v[kb].y));
            g_midT[(size_t)(kb*WW + w)*HH + h] = __float2half_rn(im);
        }
    }
}

// ===== Pass 4: fp16 conv1x1+leaky + conv3x3+leaky; int4 halo loads, rolling-window conv3x3 =====
__global__ __launch_bounds__(256) void k_conv23(const float* __restrict__ img,
                                                const float* __restrict__ w2,
                                                const float* __restrict__ b2,
                                                const float* __restrict__ wi,
                                                const float* __restrict__ bi,
                                                float* __restrict__ out){
    __shared__ float s_mid[48][66];
    int b  = blockIdx.z;
    int h0 = blockIdx.y * 32;
    int w0 = blockIdx.x * 64;
    int tid = threadIdx.x;
    bool interior = (h0 >= 8) && (h0 + 39 < HH) && (w0 >= 1) && (w0 + 64 < WW);

    const __half* midb = g_midT + (size_t)b*HW;

    float w20 = __half2float(__float2half_rn(__ldg(w2)));
    float w21 = __half2float(__float2half_rn(__ldg(w2+1)));
    float bb2 = __half2float(__float2half_rn(__ldg(b2)));
    float k0=__ldg(wi), k1=__ldg(wi+1), k2=__ldg(wi+2),
          k3=__ldg(wi+3), k4=__ldg(wi+4), k5=__ldg(wi+5),
          k6=__ldg(wi+6), k7=__ldg(wi+7), k8=__ldg(wi+8);
    float kb = __ldg(bi);

    cudaGridDependencySynchronize();

    if (interior){
        for (int i=tid; i<66*6; i+=256){
            int wl = i / 6, p = i % 6;
            int w = w0 - 1 + wl;
            int h = h0 - 8 + 8*p;
            int4 v = *(const int4*)(midb + (size_t)w*HH + h);
            const __half2* hp = (const __half2*)&v;
            #pragma unroll
            for (int q=0;q<4;q++){
                float2 f = __half22float2(hp[q]);
                s_mid[8*p + 2*q    ][wl] = f.x;
                s_mid[8*p + 2*q + 1][wl] = f.y;
            }
        }
    } else {
        for (int i=tid;i<66*36;i+=256){
            int wl = i / 36, r = i % 36;
            int w = w0 - 1 + wl, h = h0 - 2 + r;
            float v = 0.f;
            if (w>=0 && w<WW && h>=0 && h<HH)
                v = __half2float(midb[(size_t)w*HH + h]);
            s_mid[r+6][wl] = v;
        }
    }
    __syncthreads();

    const float* imgb = img + (size_t)b*HW;
    const __half2 slope2 = __half2half2(__float2half_rn(0.01f));

    if (interior){
        const unsigned long long w20p = pk2(w20,w20), w21p = pk2(w21,w21), b2p = pk2(bb2,bb2);
        for (int i=tid; i<34*32; i+=256){
            int r  = 7 + (i >> 5);
            int p  = i & 31;
            int wl = 1 + 2*p;
            int h  = h0 - 8 + r;
            int w  = w0 - 1 + wl;
            float2 ig = *(const float2*)(imgb + (size_t)h*WW + w);
            float2 igq = __half22float2(__float22half2_rn(ig));
            unsigned long long imp = pk2(s_mid[r][wl], s_mid[r][wl+1]);
            unsigned long long y  = ffma2(w20p, imp, ffma2(w21p, pk2(igq.x,igq.y), b2p));
            float y0,y1; upk2(y,y0,y1);
            __half2 yh2 = __float22half2_rn(make_float2(y0,y1));
            __half2 m2  = __hmax2(yh2, __hmul2(yh2, slope2));
            float2 mf = __half22float2(m2);
            s_mid[r][wl]   = mf.x;
            s_mid[r][wl+1] = mf.y;
        }
        if (tid < 68){
            int r  = 7 + (tid >> 1);
            int wl = (tid & 1) * 65;
            int h  = h0 - 8 + r;
            int w  = w0 - 1 + wl;
            float imh = s_mid[r][wl];
            float igh = __half2float(__float2half_rn(__ldg(&imgb[(size_t)h*WW + w])));
            float y = fmaf(w20, imh, fmaf(w21, igh, bb2));
            __half yh = __float2half_rn(y);
            __half m  = __hmax(yh, __hmul(yh, __float2half_rn(0.01f)));
            s_mid[r][wl] = __half2float(m);
        }
    } else {
        const __half slope = __float2half_rn(0.01f);
        for (int i=tid;i<34*66;i+=256){
            int rr = 1 + i/66, wl = i%66;
            int h = h0 - 2 + rr, w = w0 - 1 + wl;
            int r = rr + 6;
            float m = 0.f;
            if (h>=0 && h<HH && w>=0 && w<WW){
                float imh = s_mid[r][wl];
                float igh = __half2float(__float2half_rn(__ldg(&imgb[(size_t)h*WW + w])));
                float y = fmaf(w20, imh, fmaf(w21, igh, bb2));
                __half yh = __float2half_rn(y);
                if (__half2float(yh) < 0.f) yh = __hmul(slope, yh);
                m = __half2float(yh);
            }
            s_mid[r][wl] = m;
        }
    }
    __syncthreads();

    // phase 3: conv3x3 + leaky; 8 consecutive rows per thread, rolling 3-row register window
    {
        int wl = tid & 63, hq = tid >> 6;
        int w  = w0 + wl;
        if (w < WW){
            int r0 = 8*hq + 7;
            float a0=s_mid[r0  ][wl], a1=s_mid[r0  ][wl+1], a2=s_mid[r0  ][wl+2];
            float b0=s_mid[r0+1][wl], b1=s_mid[r0+1][wl+1], b2=s_mid[r0+1][wl+2];
            #pragma unroll
            for (int j=0;j<8;j++){
                int rr = r0 + 2 + j;
                float c0=s_mid[rr][wl], c1=s_mid[rr][wl+1], c2=s_mid[rr][wl+2];
                float acc = kb;
                acc = fmaf(k0,a0,acc); acc = fmaf(k1,a1,acc); acc = fmaf(k2,a2,acc);
                acc = fmaf(k3,b0,acc); acc = fmaf(k4,b1,acc); acc = fmaf(k5,b2,acc);
                acc = fmaf(k6,c0,acc); acc = fmaf(k7,c1,acc); acc = fmaf(k8,c2,acc);
                int h = h0 + 8*hq + j;
                out[(size_t)(b*HH + h)*WW + w] = fmaxf(acc, 0.01f*acc);
                a0=b0; a1=b1; a2=b2;
                b0=c0; b1=c1; b2=c2;
            }
        }
    }
}

// ---- PDL launch helper ----
static void launch_pdl(const void* func, dim3 grid, dim3 block, size_t smem,
                       void** args){
    cudaLaunchConfig_t cfg = {};
    cfg.gridDim = grid;
    cfg.blockDim = block;
    cfg.dynamicSmemBytes = smem;
    cfg.stream = 0;
    cudaLaunchAttribute attr[1];
    attr[0].id = cudaLaunchAttributeProgrammaticStreamSerialization;
    attr[0].val.programmaticStreamSerializationAllowed = 1;
    cfg.attrs = attr;
    cfg.numAttrs = 1;
    cudaLaunchKernelExC(&cfg, func, args);
}

extern "C" void kernel_launch(void* const* d_in, const int* in_sizes, int n_in,
                              void* d_out, int out_size){
    const float* img = (const float*)d_in[0];
    const float* ksp = (const float*)d_in[1];
    const float* wk  = (const float*)d_in[2];
    const float* bk  = (const float*)d_in[3];
    const float* w1  = (const float*)d_in[4];
    const float* b1  = (const float*)d_in[5];
    const float* w2  = (const float*)d_in[6];
    const float* b2  = (const float*)d_in[7];
    const float* wi  = (const float*)d_in[8];
    const float* bi  = (const float*)d_in[9];
    float* out = (float*)d_out;

    cudaFuncSetAttribute(k_fftw,  cudaFuncAttributeMaxDynamicSharedMemorySize, FFTW_SMEM);
    cudaFuncSetAttribute(k_ffthb, cudaFuncAttributeMaxDynamicSharedMemorySize, FFTHB_SMEM);

    // diagnostic: 3 nops shift abs launch index 3 onto k_conv1
    k_nop<<<1, 32>>>();
    k_nop<<<1, 32>>>();
    k_nop<<<1, 32>>>();

    k_conv1<<<(NTOT/8 + 127)/128, 128>>>(ksp, wk, bk, w1, b1);

    {
        void* args[] = {};
        launch_pdl((const void*)k_fftw, dim3(8*80), dim3(128), FFTW_SMEM, args);
    }
    {
        void* args[] = {};
        launch_pdl((const void*)k_ffthb, dim3(WW), dim3(640), FFTHB_SMEM, args);
    }
    {
        void* args[] = { (void*)&img, (void*)&w2, (void*)&b2, (void*)&wi, (void*)&bi, (void*)&out };
        dim3 gD((WW+63)/64, (HH+31)/32, BB);
        launch_pdl((const void*)k_conv23, gD, dim3(256), 0, args);
    }
}

// round 16
// speedup vs baseline: 1.0907x; 1.0907x over previous
#include <cuda_runtime.h>
#include <cuda_fp16.h>

// Problem dims
#define BB 8
#define HH 640
#define WW 368
#define HW (HH*WW)            // 235520
#define NTOT (BB*HH*WW)       // 1884160

// Static device scratch
__device__ float2 g_bufA[NTOT];   // conv output as complex, [b][h][w]
__device__ float2 g_bufB[NTOT];   // after W-FFT, transposed: [b][w][h]
__device__ __half g_midT[NTOT];   // |ifft| (fp16-quantized), [b][w][h]

// Transformed conv1 weights: computed by k_prep, copied into constant bank
struct ConstPack {
    unsigned long long U[32*36];   // Winograd U, splatted (v,v)
    ulonglong2         bw[32];     // (bk splat, w1a splat)
    unsigned long long w1b[32];    // w1 ch1 splat
    float              b1[2];
};
__device__   ConstPack g_stage;
__constant__ ConstPack cCP;

// ---------------- packed f32x2 helpers ----------------
__device__ __forceinline__ unsigned long long pk2(float lo, float hi){
    unsigned long long r; asm("mov.b64 %0, {%1,%2};" : "=l"(r) : "f"(lo), "f"(hi)); return r;
}
__device__ __forceinline__ void upk2(unsigned long long v, float& lo, float& hi){
    asm("mov.b64 {%0,%1}, %2;" : "=f"(lo), "=f"(hi) : "l"(v));
}
__device__ __forceinline__ unsigned long long ffma2(unsigned long long a, unsigned long long b, unsigned long long c){
    unsigned long long d; asm("fma.rn.f32x2 %0, %1, %2, %3;" : "=l"(d) : "l"(a), "l"(b), "l"(c)); return d;
}
__device__ __forceinline__ unsigned long long fmul2(unsigned long long a, unsigned long long b){
    unsigned long long d; asm("mul.rn.f32x2 %0, %1, %2;" : "=l"(d) : "l"(a), "l"(b)); return d;
}
__device__ __forceinline__ unsigned long long fadd2(unsigned long long a, unsigned long long b){
    unsigned long long d; asm("add.rn.f32x2 %0, %1, %2;" : "=l"(d) : "l"(a), "l"(b)); return d;
}
// packed leaky: 0.505*x + 0.495*|x|
__device__ __forceinline__ unsigned long long leaky2(unsigned long long x,
                                                     unsigned long long cA,
                                                     unsigned long long cB){
    unsigned long long ax;
    asm("and.b64 %0, %1, 0x7FFFFFFF7FFFFFFF;" : "=l"(ax) : "l"(x));
    return ffma2(x, cA, fmul2(ax, cB));
}
__device__ __forceinline__ float sqrt_approx(float x){
    float r; asm("sqrt.approx.f32 %0, %1;" : "=f"(r) : "f"(x)); return r;
}

// ---------------- complex helpers (IFFT sign: e^{+2 pi i / N}) ----------------
__device__ __forceinline__ float2 cadd(float2 a, float2 b){ return make_float2(a.x+b.x, a.y+b.y); }
__device__ __forceinline__ float2 csub(float2 a, float2 b){ return make_float2(a.x-b.x, a.y-b.y); }
__device__ __forceinline__ float2 cmul(float2 a, float2 b){
    return make_float2(fmaf(a.x,b.x,-(a.y*b.y)), fmaf(a.x,b.y, a.y*b.x));
}
__device__ __forceinline__ float2 cmuli(float2 a){ return make_float2(-a.y, a.x); }

__device__ __forceinline__ void dft4p(float2 a, float2 b, float2 c, float2 d,
                                      float2& x0, float2& x1, float2& x2, float2& x3){
    float2 t0 = cadd(a,c), t1 = csub(a,c), t2 = cadd(b,d), t3 = csub(b,d);
    x0 = cadd(t0,t2); x2 = csub(t0,t2);
    float2 it3 = cmuli(t3);
    x1 = cadd(t1,it3); x3 = csub(t1,it3);
}

#define R2F  0.70710678118654752f
#define C8F  0.92387953251128674f
#define S8F  0.38268343236508977f

__device__ __forceinline__ void fft16(float2 v[16]){
    float2 Bm[4][4];
    #pragma unroll
    for (int n1=0;n1<4;n1++)
        dft4p(v[n1], v[n1+4], v[n1+8], v[n1+12], Bm[n1][0],Bm[n1][1],Bm[n1][2],Bm[n1][3]);
    Bm[1][1] = cmul(Bm[1][1], make_float2( C8F,  S8F));
    Bm[1][2] = cmul(Bm[1][2], make_float2( R2F,  R2F));
    Bm[1][3] = cmul(Bm[1][3], make_float2( S8F,  C8F));
    Bm[2][1] = cmul(Bm[2][1], make_float2( R2F,  R2F));
    Bm[2][2] = cmuli(Bm[2][2]);
    Bm[2][3] = cmul(Bm[2][3], make_float2(-R2F,  R2F));
    Bm[3][1] = cmul(Bm[3][1], make_float2( S8F,  C8F));
    Bm[3][2] = cmul(Bm[3][2], make_float2(-R2F,  R2F));
    Bm[3][3] = cmul(Bm[3][3], make_float2(-C8F, -S8F));
    #pragma unroll
    for (int k2=0;k2<4;k2++)
        dft4p(Bm[0][k2],Bm[1][k2],Bm[2][k2],Bm[3][k2], v[k2], v[k2+4], v[k2+8], v[k2+12]);
}

__device__ __forceinline__ void fft8(float2 v[8]){
    float2 E0,E1,E2,E3,O0,O1,O2,O3;
    dft4p(v[0],v[2],v[4],v[6], E0,E1,E2,E3);
    dft4p(v[1],v[3],v[5],v[7], O0,O1,O2,O3);
    O1 = cmul(O1, make_float2( R2F, R2F));
    O2 = cmuli(O2);
    O3 = cmul(O3, make_float2(-R2F, R2F));
    v[0]=cadd(E0,O0); v[4]=csub(E0,O0);
    v[1]=cadd(E1,O1); v[5]=csub(E1,O1);
    v[2]=cadd(E2,O2); v[6]=csub(E2,O2);
    v[3]=cadd(E3,O3); v[7]=csub(E3,O3);
}

__device__ __forceinline__ void dft5p(float2 x0,float2 x1,float2 x2,float2 x3,float2 x4, float2* X){
    const float c1 =  0.30901699437494742f, s1 = 0.95105651629515357f;
    const float c2 = -0.80901699437494742f, s2 = 0.58778525229247312f;
    float2 t1=cadd(x1,x4), t2=csub(x1,x4), t3=cadd(x2,x3), t4=csub(x2,x3);
    X[0] = cadd(x0, cadd(t1,t3));
    float2 a1 = make_float2(x0.x + c1*t1.x + c2*t3.x, x0.y + c1*t1.y + c2*t3.y);
    float2 b1 = make_float2(s1*t2.x + s2*t4.x,        s1*t2.y + s2*t4.y);
    float2 a2 = make_float2(x0.x + c2*t1.x + c1*t3.x, x0.y + c2*t1.y + c1*t3.y);
    float2 b2 = make_float2(s2*t2.x - s1*t4.x,        s2*t2.y - s1*t4.y);
    float2 ib1 = cmuli(b1), ib2 = cmuli(b2);
    X[1]=cadd(a1,ib1); X[4]=csub(a1,ib1);
    X[2]=cadd(a2,ib2); X[3]=csub(a2,ib2);
}

// ===== Pass 0: weight transform into g_stage (one tiny block) =====
__global__ void k_prep(const float* __restrict__ wk,
                       const float* __restrict__ bk,
                       const float* __restrict__ w1,
                       const float* __restrict__ b1){
    int tid = threadIdx.x;
    if (tid < 192){
        int o = tid/6, rw = tid%6;
        float g0 = wk[o*18 + rw*3 + 0];
        float g1 = wk[o*18 + rw*3 + 1];
        float g2 = wk[o*18 + rw*3 + 2];
        float u0 = 0.25f*g0;
        float u1 = -(g0+g1+g2)*(1.f/6.f);
        float u2 = (g1-g0-g2)*(1.f/6.f);
        float u3 = fmaf(2.f,g1, fmaf(4.f,g2, g0))*(1.f/24.f);
        float u4 = fmaf(-2.f,g1, fmaf(4.f,g2, g0))*(1.f/24.f);
        float u5 = g2;
        unsigned long long* Uo = &g_stage.U[o*36 + rw*6];
        Uo[0]=pk2(u0,u0); Uo[1]=pk2(u1,u1); Uo[2]=pk2(u2,u2);
        Uo[3]=pk2(u3,u3); Uo[4]=pk2(u4,u4); Uo[5]=pk2(u5,u5);
    }
    if (tid < 32){
        float v=bk[tid]; float a=w1[tid]; float bq=w1[32+tid];
        g_stage.bw[tid]  = make_ulonglong2(pk2(v,v), pk2(a,a));
        g_stage.w1b[tid] = pk2(bq,bq);
    }
    if (tid < 2) g_stage.b1[tid] = b1[tid];
}

// ===== Pass 1: Winograd F(4,3) conv3x3(2->32)+leaky + conv1x1(32->2)+leaky.
//       Weights from __constant__ (no smem, no syncs, constant-cache port). =====
__global__ __launch_bounds__(128) void k_conv1(const float* __restrict__ ks){
    int tid = threadIdx.x;
    int t = blockIdx.x*blockDim.x + tid;            // thread = 8 px
    int g   = t % 46;
    int row = t / 46;
    int h = row % HH;
    int b = row / HH;
    int w0 = g*8;

    const unsigned long long c2p  = pk2( 2.f, 2.f);
    const unsigned long long cm2p = pk2(-2.f,-2.f);
    const unsigned long long c4p  = pk2( 4.f, 4.f);
    const unsigned long long cm4p = pk2(-4.f,-4.f);
    const unsigned long long cm5p = pk2(-5.f,-5.f);
    const unsigned long long c8p  = pk2( 8.f, 8.f);
    const unsigned long long cm1p = pk2(-1.f,-1.f);

    unsigned long long tp[36];
    #pragma unroll
    for (int c=0;c<2;c++){
        const float* base = ks + (size_t)(b*2+c)*HW;
        #pragma unroll
        for (int kh=0;kh<3;kh++){
            int hh = h + kh - 1;
            float4 f1 = make_float4(0.f,0.f,0.f,0.f);
            float4 f2 = f1;
            float xm1 = 0.f, xp8 = 0.f;
            if (hh>=0 && hh<HH){
                const float* rp = base + (size_t)hh*WW + w0;
                f1 = *(const float4*)rp;
                f2 = *(const float4*)(rp+4);
                xm1 = (g>0)  ? __ldg(rp-1) : 0.f;
                xp8 = (g<45) ? __ldg(rp+8) : 0.f;
            }
            unsigned long long dp0 = pk2(xm1,  f1.w);
            unsigned long long dp1 = pk2(f1.x, f2.x);
            unsigned long long dp2 = pk2(f1.y, f2.y);
            unsigned long long dp3 = pk2(f1.z, f2.z);
            unsigned long long dp4 = pk2(f1.w, f2.w);
            unsigned long long dp5 = pk2(f2.x, xp8);
            unsigned long long* tr = &tp[(c*3+kh)*6];
            tr[0] = ffma2(dp0, c4p, ffma2(dp2, cm5p, dp4));
            tr[1] = ffma2(fadd2(dp1,dp2), cm4p, fadd2(dp3,dp4));
            unsigned long long d12 = ffma2(dp2, cm1p, dp1);
            unsigned long long d43 = ffma2(dp3, cm1p, dp4);
            tr[2] = ffma2(d12, c4p, d43);
            unsigned long long e = ffma2(dp1, cm1p, dp3);
            unsigned long long f = ffma2(dp2, cm1p, dp4);
            tr[3] = ffma2(e, c2p,  f);
            tr[4] = ffma2(e, cm2p, f);
            tr[5] = ffma2(dp1, c4p, ffma2(dp3, cm5p, dp5));
        }
    }

    unsigned long long acc0[4], acc1[4];
    {
        unsigned long long b0 = pk2(cCP.b1[0], cCP.b1[0]);
        unsigned long long b1p = pk2(cCP.b1[1], cCP.b1[1]);
        #pragma unroll
        for (int j=0;j<4;j++){ acc0[j]=b0; acc1[j]=b1p; }
    }
    const unsigned long long cA = pk2(0.505f,0.505f);
    const unsigned long long cB = pk2(0.495f,0.495f);

    #pragma unroll 2
    for (int o=0;o<32;o++){
        const unsigned long long* Uo = &cCP.U[o*36];
        unsigned long long m0,m1,m2,m3,m4,m5;
        m0 = fmul2(Uo[0], tp[0]); m1 = fmul2(Uo[1], tp[1]); m2 = fmul2(Uo[2], tp[2]);
        m3 = fmul2(Uo[3], tp[3]); m4 = fmul2(Uo[4], tp[4]); m5 = fmul2(Uo[5], tp[5]);
        #pragma unroll
        for (int rw=1;rw<6;rw++){
            const unsigned long long* Ur = &Uo[rw*6];
            const unsigned long long* tr = &tp[rw*6];
            m0 = ffma2(Ur[0], tr[0], m0);
            m1 = ffma2(Ur[1], tr[1], m1);
            m2 = ffma2(Ur[2], tr[2], m2);
            m3 = ffma2(Ur[3], tr[3], m3);
            m4 = ffma2(Ur[4], tr[4], m4);
            m5 = ffma2(Ur[5], tr[5], m5);
        }
        ulonglong2 bw = cCP.bw[o];
        unsigned long long bkp = bw.x, wa = bw.y;
        unsigned long long wb = cCP.w1b[o];
        unsigned long long ta = fadd2(m1,m2);
        unsigned long long tb = ffma2(m2, cm1p, m1);
        unsigned long long tc = fadd2(m3,m4);
        unsigned long long td = ffma2(m4, cm1p, m3);
        unsigned long long y0 = fadd2(fadd2(m0,ta), fadd2(tc,bkp));
        unsigned long long y1 = ffma2(td, c2p, fadd2(tb,bkp));
        unsigned long long y2 = ffma2(tc, c4p, fadd2(ta,bkp));
        unsigned long long y3 = ffma2(td, c8p, fadd2(tb, fadd2(m5,bkp)));
        y0 = leaky2(y0, cA, cB); y1 = leaky2(y1, cA, cB);
        y2 = leaky2(y2, cA, cB); y3 = leaky2(y3, cA, cB);
        acc0[0] = ffma2(wa, y0, acc0[0]);  acc1[0] = ffma2(wb, y0, acc1[0]);
        acc0[1] = ffma2(wa, y1, acc0[1]);  acc1[1] = ffma2(wb, y1, acc1[1]);
        acc0[2] = ffma2(wa, y2, acc0[2]);  acc1[2] = ffma2(wb, y2, acc1[2]);
        acc0[3] = ffma2(wa, y3, acc0[3]);  acc1[3] = ffma2(wb, y3, acc1[3]);
    }

    float r[8], im[8];
    #pragma unroll
    for (int j=0;j<4;j++){
        float lo,hi;
        upk2(acc0[j],lo,hi); r[j]  = fmaxf(lo,0.01f*lo); r[4+j]  = fmaxf(hi,0.01f*hi);
        upk2(acc1[j],lo,hi); im[j] = fmaxf(lo,0.01f*lo); im[4+j] = fmaxf(hi,0.01f*hi);
    }
    float sg = ((b+h)&1) ? -1.f : 1.f;     // w0 even
    float4* dst = (float4*)&g_bufA[(size_t)row*WW + w0];
    #pragma unroll
    for (int k2=0;k2<4;k2++){
        dst[k2] = make_float4( sg*r[2*k2],  sg*im[2*k2], -sg*r[2*k2+1], -sg*im[2*k2+1]);
    }
}

// ===== Pass 2: W-FFT (368 = 23 x 16), 8 rows/block, 128 threads =====
#define FFTW_ROWS 8
#define ROWSTRIDE 369
#define FFTW_SMEM (FFTW_ROWS*ROWSTRIDE*8 + 368*8 + 23*8*2)

__global__ __launch_bounds__(128) void k_fftw(){
    extern __shared__ unsigned char dsm[];
    float2* S     = (float2*)dsm;
    float2* tw368 = (float2*)(dsm + FFTW_ROWS*ROWSTRIDE*8);
    unsigned long long* twc = (unsigned long long*)(dsm + FFTW_ROWS*ROWSTRIDE*8 + 368*8);
    unsigned long long* tws = twc + 23;

    int b  = blockIdx.x / 80;
    int h0 = (blockIdx.x % 80) * FFTW_ROWS;
    int tid = threadIdx.x;
    const float2* src = g_bufA + (size_t)(b*HH + h0)*WW;

    for (int m=tid;m<368;m+=128){ float sn,cs; sincospif((float)m*(1.f/184.f), &sn,&cs); tw368[m]=make_float2(cs,sn); }
    if (tid < 23){ float sn,cs; sincospif((float)tid*(2.f/23.f), &sn,&cs); twc[tid]=pk2(cs,cs); tws[tid]=pk2(sn,sn); }

    cudaGridDependencySynchronize();

    for (int t=tid; t<FFTW_ROWS*184; t+=128){
        int r = t / 184, c2 = t % 184;
        float4 v = ((const float4*)src)[t];
        float2* drow = &S[r*ROWSTRIDE + 2*c2];
        drow[0] = make_float2(v.x, v.y);
        drow[1] = make_float2(v.z, v.w);
    }
    __syncthreads();

    for (int t=tid; t<FFTW_ROWS*23; t+=128){
        int r = t / 23, n1 = t % 23;
        float2* rowp = &S[r*ROWSTRIDE];
        float2 v[16];
        #pragma unroll
        for (int j=0;j<16;j++) v[j] = rowp[n1 + 23*j];
        fft16(v);
        #pragma unroll
        for (int k2=1;k2<16;k2++) v[k2] = cmul(v[k2], tw368[n1*k2]);
        #pragma unroll
        for (int k2=0;k2<16;k2++) rowp[n1 + 23*k2] = v[k2];
    }
    __syncthreads();

    {
        int r = tid >> 4, k2 = tid & 15;
        float2* rowp = &S[r*ROWSTRIDE];
        float2 a[23];
        #pragma unroll
        for (int n=0;n<23;n++) a[n] = rowp[23*k2 + n];
        __syncthreads();

        float2 a0 = a[0];
        unsigned long long ps[11], pd[11];
        float2 x0 = a0;
        #pragma unroll
        for (int n=1;n<=11;n++){
            float2 s = cadd(a[n], a[23-n]);
            float2 d = csub(a[n], a[23-n]);
            x0 = cadd(x0, s);
            ps[n-1] = pk2(s.x, s.y);
            pd[n-1] = pk2(d.x, d.y);
        }
        rowp[k2] = x0;
        unsigned long long pa0 = pk2(a0.x, a0.y);
        const unsigned long long pz = pk2(0.f, 0.f);
        for (int k=1;k<=11;k++){
            unsigned long long C = pa0, Sm = pz;
            int m = 0;
            #pragma unroll
            for (int n=1;n<=11;n++){
                m += k; if (m >= 23) m -= 23;
                C  = ffma2(ps[n-1], twc[m], C);
                Sm = ffma2(pd[n-1], tws[m], Sm);
            }
            float Cx,Cy,Sx,Sy;
            upk2(C,Cx,Cy); upk2(Sm,Sx,Sy);
            rowp[k2 + 16*k]      = make_float2(Cx - Sy, Cy + Sx);
            rowp[k2 + 16*(23-k)] = make_float2(Cx + Sy, Cy - Sx);
        }
    }
    __syncthreads();

    for (int i=tid;i<FFTW_ROWS*368;i+=128){
        int r2 = i & 7; int w = i >> 3;
        g_bufB[(size_t)(b*WW + w)*HH + h0 + r2] = S[r2*ROWSTRIDE + w];
    }
}

// ===== Pass 3: H-FFT + B-DFT-8 + abs; PDL: twiddles before grid sync =====
#define HROW 740
#define HCHUNK 148
#define FFTHB_SMEM (8*HROW*8 + 640*8 + 128*8)

__global__ __launch_bounds__(640) void k_ffthb(){
    extern __shared__ unsigned char dsm[];
    float2* S    = (float2*)dsm;
    float2* W640 = (float2*)(dsm + 8*HROW*8);
    float2* W128 = (float2*)(dsm + 8*HROW*8 + 640*8);
    int w   = blockIdx.x;
    int tid = threadIdx.x;

    { float sn,cs; sincospif((float)tid*(1.f/320.f),&sn,&cs); W640[tid]=make_float2(cs,sn); }
    if (tid<128){ float sn,cs; sincospif((float)tid*(1.f/64.f),&sn,&cs); W128[tid]=make_float2(cs,sn); }

    cudaGridDependencySynchronize();

    for (int i=tid;i<8*640;i+=640){
        int bb = i/640, h = i%640;
        S[bb*HROW + h] = g_bufB[(size_t)(bb*WW + w)*HH + h];
    }
    __syncthreads();

    {
        float2 Xa[5], Xb[5];
        int rowa = tid >> 7, n2a = tid & 127;
        {
            float2* col = &S[rowa*HROW];
            dft5p(col[n2a], col[n2a+128], col[n2a+256], col[n2a+384], col[n2a+512], Xa);
            #pragma unroll
            for (int k1=1;k1<5;k1++) Xa[k1] = cmul(Xa[k1], W640[n2a*k1]);
        }
        int rowb = 0, n2b = 0;
        if (tid < 384){
            int t2 = tid + 640;
            rowb = t2 >> 7; n2b = t2 & 127;
            float2* col = &S[rowb*HROW];
            dft5p(col[n2b], col[n2b+128], col[n2b+256], col[n2b+384], col[n2b+512], Xb);
            #pragma unroll
            for (int k1=1;k1<5;k1++) Xb[k1] = cmul(Xb[k1], W640[n2b*k1]);
        }
        __syncthreads();
        {
            int p2 = (n2a>>3) + 17*(n2a&7);
            float2* rowp = &S[rowa*HROW];
            #pragma unroll
            for (int k1=0;k1<5;k1++) rowp[k1*HCHUNK + p2] = Xa[k1];
        }
        if (tid < 384){
            int p2 = (n2b>>3) + 17*(n2b&7);
            float2* rowp = &S[rowb*HROW];
            #pragma unroll
            for (int k1=0;k1<5;k1++) rowp[k1*HCHUNK + p2] = Xb[k1];
        }
    }
    __syncthreads();

    {
        float2 v[16];
        int brow=0, chunk=0, m1=0;
        bool act = (tid < 320);
        if (act){
            brow = tid/40; int rest = tid%40; chunk = rest/8; m1 = rest%8;
            float2* base = &S[brow*HROW + chunk*HCHUNK];
            #pragma unroll
            for (int m2=0;m2<16;m2++) v[m2] = base[m2 + 17*m1];
            fft16(v);
            #pragma unroll
            for (int kk=1;kk<16;kk++) v[kk] = cmul(v[kk], W128[m1*kk]);
        }
        __syncthreads();
        if (act){
            float2* base = &S[brow*HROW + chunk*HCHUNK];
            #pragma unroll
            for (int kk=0;kk<16;kk++) base[m1 + 9*kk] = v[kk];
        }
    }
    __syncthreads();

    {
        int brow = tid/80; int rest = tid%80; int k1 = rest/16; int q2 = rest%16;
        float2* rowp = &S[brow*HROW];
        float2 v[8];
        #pragma unroll
        for (int m1=0;m1<8;m1++) v[m1] = rowp[k1*HCHUNK + m1 + 9*q2];
        __syncthreads();
        fft8(v);
        #pragma unroll
        for (int q1=0;q1<8;q1++) rowp[k1 + 5*(q2 + 16*q1)] = v[q1];
    }
    __syncthreads();

    {
        int h = tid;
        float2 v[8];
        #pragma unroll
        for (int bb=0;bb<8;bb++) v[bb] = S[bb*HROW + h];
        fft8(v);
        const float SC = 7.2851736e-4f;
        #pragma unroll
        for (int kb=0;kb<8;kb++){
            float im = SC * sqrt_approx(fmaf(v[kb].x, v[kb].x, v[kb].y*v[kb].y));
            g_midT[(size_t)(kb*WW + w)*HH + h] = __float2half_rn(im);
        }
    }
}

// ===== Pass 4: fp16 conv1x1+leaky + conv3x3+leaky; int4 halo loads, rolling-window conv3x3 =====
__global__ __launch_bounds__(256) void k_conv23(const float* __restrict__ img,
                                                const float* __restrict__ w2,
                                                const float* __restrict__ b2,
                                                const float* __restrict__ wi,
                                                const float* __restrict__ bi,
                                                float* __restrict__ out){
    __shared__ float s_mid[48][66];
    int b  = blockIdx.z;
    int h0 = blockIdx.y * 32;
    int w0 = blockIdx.x * 64;
    int tid = threadIdx.x;
    bool interior = (h0 >= 8) && (h0 + 39 < HH) && (w0 >= 1) && (w0 + 64 < WW);

    const __half* midb = g_midT + (size_t)b*HW;

    float w20 = __half2float(__float2half_rn(__ldg(w2)));
    float w21 = __half2float(__float2half_rn(__ldg(w2+1)));
    float bb2 = __half2float(__float2half_rn(__ldg(b2)));
    float k0=__ldg(wi), k1=__ldg(wi+1), k2=__ldg(wi+2),
          k3=__ldg(wi+3), k4=__ldg(wi+4), k5=__ldg(wi+5),
          k6=__ldg(wi+6), k7=__ldg(wi+7), k8=__ldg(wi+8);
    float kb = __ldg(bi);

    cudaGridDependencySynchronize();

    if (interior){
        for (int i=tid; i<66*6; i+=256){
            int wl = i / 6, p = i % 6;
            int w = w0 - 1 + wl;
            int h = h0 - 8 + 8*p;
            int4 v = *(const int4*)(midb + (size_t)w*HH + h);
            const __half2* hp = (const __half2*)&v;
            #pragma unroll
            for (int q=0;q<4;q++){
                float2 f = __half22float2(hp[q]);
                s_mid[8*p + 2*q    ][wl] = f.x;
                s_mid[8*p + 2*q + 1][wl] = f.y;
            }
        }
    } else {
        for (int i=tid;i<66*36;i+=256){
            int wl = i / 36, r = i % 36;
            int w = w0 - 1 + wl, h = h0 - 2 + r;
            float v = 0.f;
            if (w>=0 && w<WW && h>=0 && h<HH)
                v = __half2float(midb[(size_t)w*HH + h]);
            s_mid[r+6][wl] = v;
        }
    }
    __syncthreads();

    const float* imgb = img + (size_t)b*HW;
    const __half2 slope2 = __half2half2(__float2half_rn(0.01f));

    if (interior){
        const unsigned long long w20p = pk2(w20,w20), w21p = pk2(w21,w21), b2p = pk2(bb2,bb2);
        for (int i=tid; i<34*32; i+=256){
            int r  = 7 + (i >> 5);
            int p  = i & 31;
            int wl = 1 + 2*p;
            int h  = h0 - 8 + r;
            int w  = w0 - 1 + wl;
            float2 ig = *(const float2*)(imgb + (size_t)h*WW + w);
            float2 igq = __half22float2(__float22half2_rn(ig));
            unsigned long long imp = pk2(s_mid[r][wl], s_mid[r][wl+1]);
            unsigned long long y  = ffma2(w20p, imp, ffma2(w21p, pk2(igq.x,igq.y), b2p));
            float y0,y1; upk2(y,y0,y1);
            __half2 yh2 = __float22half2_rn(make_float2(y0,y1));
            __half2 m2  = __hmax2(yh2, __hmul2(yh2, slope2));
            float2 mf = __half22float2(m2);
            s_mid[r][wl]   = mf.x;
            s_mid[r][wl+1] = mf.y;
        }
        if (tid < 68){
            int r  = 7 + (tid >> 1);
            int wl = (tid & 1) * 65;
            int h  = h0 - 8 + r;
            int w  = w0 - 1 + wl;
            float imh = s_mid[r][wl];
            float igh = __half2float(__float2half_rn(__ldg(&imgb[(size_t)h*WW + w])));
            float y = fmaf(w20, imh, fmaf(w21, igh, bb2));
            __half yh = __float2half_rn(y);
            __half m  = __hmax(yh, __hmul(yh, __float2half_rn(0.01f)));
            s_mid[r][wl] = __half2float(m);
        }
    } else {
        const __half slope = __float2half_rn(0.01f);
        for (int i=tid;i<34*66;i+=256){
            int rr = 1 + i/66, wl = i%66;
            int h = h0 - 2 + rr, w = w0 - 1 + wl;
            int r = rr + 6;
            float m = 0.f;
            if (h>=0 && h<HH && w>=0 && w<WW){
                float imh = s_mid[r][wl];
                float igh = __half2float(__float2half_rn(__ldg(&imgb[(size_t)h*WW + w])));
                float y = fmaf(w20, imh, fmaf(w21, igh, bb2));
                __half yh = __float2half_rn(y);
                if (__half2float(yh) < 0.f) yh = __hmul(slope, yh);
                m = __half2float(yh);
            }
            s_mid[r][wl] = m;
        }
    }
    __syncthreads();

    // phase 3: conv3x3 + leaky; 8 consecutive rows per thread, rolling 3-row register window
    {
        int wl = tid & 63, hq = tid >> 6;
        int w  = w0 + wl;
        if (w < WW){
            int r0 = 8*hq + 7;
            float a0=s_mid[r0  ][wl], a1=s_mid[r0  ][wl+1], a2=s_mid[r0  ][wl+2];
            float b0=s_mid[r0+1][wl], b1=s_mid[r0+1][wl+1], b2=s_mid[r0+1][wl+2];
            #pragma unroll
            for (int j=0;j<8;j++){
                int rr = r0 + 2 + j;
                float c0=s_mid[rr][wl], c1=s_mid[rr][wl+1], c2=s_mid[rr][wl+2];
                float acc = kb;
                acc = fmaf(k0,a0,acc); acc = fmaf(k1,a1,acc); acc = fmaf(k2,a2,acc);
                acc = fmaf(k3,b0,acc); acc = fmaf(k4,b1,acc); acc = fmaf(k5,b2,acc);
                acc = fmaf(k6,c0,acc); acc = fmaf(k7,c1,acc); acc = fmaf(k8,c2,acc);
                int h = h0 + 8*hq + j;
                out[(size_t)(b*HH + h)*WW + w] = fmaxf(acc, 0.01f*acc);
                a0=b0; a1=b1; a2=b2;
                b0=c0; b1=c1; b2=c2;
            }
        }
    }
}

// ---- PDL launch helper ----
static void launch_pdl(const void* func, dim3 grid, dim3 block, size_t smem,
                       void** args){
    cudaLaunchConfig_t cfg = {};
    cfg.gridDim = grid;
    cfg.blockDim = block;
    cfg.dynamicSmemBytes = smem;
    cfg.stream = 0;
    cudaLaunchAttribute attr[1];
    attr[0].id = cudaLaunchAttributeProgrammaticStreamSerialization;
    attr[0].val.programmaticStreamSerializationAllowed = 1;
    cfg.attrs = attr;
    cfg.numAttrs = 1;
    cudaLaunchKernelExC(&cfg, func, args);
}

extern "C" void kernel_launch(void* const* d_in, const int* in_sizes, int n_in,
                              void* d_out, int out_size){
    const float* img = (const float*)d_in[0];
    const float* ksp = (const float*)d_in[1];
    const float* wk  = (const float*)d_in[2];
    const float* bk  = (const float*)d_in[3];
    const float* w1  = (const float*)d_in[4];
    const float* b1  = (const float*)d_in[5];
    const float* w2  = (const float*)d_in[6];
    const float* b2  = (const float*)d_in[7];
    const float* wi  = (const float*)d_in[8];
    const float* bi  = (const float*)d_in[9];
    float* out = (float*)d_out;

    cudaFuncSetAttribute(k_fftw,  cudaFuncAttributeMaxDynamicSharedMemorySize, FFTW_SMEM);
    cudaFuncSetAttribute(k_ffthb, cudaFuncAttributeMaxDynamicSharedMemorySize, FFTHB_SMEM);

    // Pass 0: compute transformed weights, copy into constant bank (D2D memcpy node)
    k_prep<<<1, 192>>>(wk, bk, w1, b1);
    void* stage_ptr = nullptr;
    cudaGetSymbolAddress(&stage_ptr, g_stage);
    cudaMemcpyToSymbolAsync(cCP, stage_ptr, sizeof(ConstPack), 0,
                            cudaMemcpyDeviceToDevice, 0);

    k_conv1<<<(NTOT/8 + 127)/128, 128>>>(ksp);

    {
        void* args[] = {};
        launch_pdl((const void*)k_fftw, dim3(8*80), dim3(128), FFTW_SMEM, args);
    }
    {
        void* args[] = {};
        launch_pdl((const void*)k_ffthb, dim3(WW), dim3(640), FFTHB_SMEM, args);
    }
    {
        void* args[] = { (void*)&img, (void*)&w2, (void*)&b2, (void*)&wi, (void*)&bi, (void*)&out };
        dim3 gD((WW+63)/64, (HH+31)/32, BB);
        launch_pdl((const void*)k_conv23, gD, dim3(256), 0, args);
    }
}